// round 3
// baseline (speedup 1.0000x reference)
#include <cuda_runtime.h>
#include <math.h>

#define BSZ 8
#define NP  1024
#define KNB 20
#define CT  169
#define EPSF 1e-6f
#define NT  8

// ---------------- scratch (device globals; no runtime allocation) ----------------
__device__ float  g_h[BSZ * 3 * NP];                       // (B,1,3,N) layer-1 input
__device__ float  g_xx[BSZ * NP];
__device__ float  g_dist[(size_t)BSZ * NP * NP];           // 32 MB distance matrix
__device__ int    g_idx[BSZ * NP * KNB];
__device__ float  g_feat[BSZ * CT * 3 * NP];               // x1|x2|x3|x4 concat channels
__device__ float  g_p[(size_t)BSZ * NP * KNB * 85 * 3];    // 167 MB  (reused as p5)
__device__ float  g_d[(size_t)BSZ * NP * KNB * 85 * 3];    // 167 MB  (reused as d5)
__device__ double g_stats[682];                            // per-channel sum, sumsq
__device__ float  g_mu[341];
__device__ float  g_rstd[341];

// ---------------- kernels ----------------

__global__ void transpose_x_kernel(const float* __restrict__ x) {
    int i = blockIdx.x * blockDim.x + threadIdx.x;   // over B*N*3
    if (i >= BSZ * NP * 3) return;
    int e = i % 3;
    int n = (i / 3) % NP;
    int b = i / (3 * NP);
    g_h[(b * 3 + e) * NP + n] = x[i];
}

__global__ void xx_kernel(const float* __restrict__ f, int bstride, int D) {
    int b = blockIdx.y;
    int n = blockIdx.x * blockDim.x + threadIdx.x;
    const float* fb = f + (size_t)b * bstride;
    float s = 0.f;
    for (int d = 0; d < D; d++) {
        float v = fb[d * NP + n];
        s += v * v;
    }
    g_xx[b * NP + n] = s;
}

// pd[b][i][j] = 2*dot(f_i,f_j) - xx_i - xx_j   (== reference formula)
__global__ void knn_dist_kernel(const float* __restrict__ f, int bstride, int D) {
    __shared__ float sI[8][32];
    __shared__ float sJ[8][32];
    int b  = blockIdx.z;
    int j0 = blockIdx.x * 32;
    int i0 = blockIdx.y * 32;
    int tx = threadIdx.x, ty = threadIdx.y;
    const float* fb = f + (size_t)b * bstride;
    float acc[4] = {0.f, 0.f, 0.f, 0.f};
    for (int d0 = 0; d0 < D; d0 += 8) {
        int d = d0 + ty;
        sI[ty][tx] = (d < D) ? fb[d * NP + i0 + tx] : 0.f;
        sJ[ty][tx] = (d < D) ? fb[d * NP + j0 + tx] : 0.f;
        __syncthreads();
#pragma unroll
        for (int dd = 0; dd < 8; dd++) {
            float vj = sJ[dd][tx];
#pragma unroll
            for (int r = 0; r < 4; r++) acc[r] += sI[dd][ty + 8 * r] * vj;
        }
        __syncthreads();
    }
    float xj = g_xx[b * NP + j0 + tx];
#pragma unroll
    for (int r = 0; r < 4; r++) {
        int i = i0 + ty + 8 * r;
        g_dist[((size_t)b * NP + i) * NP + j0 + tx] = 2.f * acc[r] - g_xx[b * NP + i] - xj;
    }
}

// stable top-K per row (ties -> lower index first, matching jax.lax.top_k)
__global__ void knn_topk_kernel() {
    int row = blockIdx.x * blockDim.x + threadIdx.x;  // b*NP + i
    if (row >= BSZ * NP) return;
    const float* dr = &g_dist[(size_t)row * NP];
    float vals[KNB];
    int   inds[KNB];
#pragma unroll
    for (int t = 0; t < KNB; t++) { vals[t] = -3.402823466e38f; inds[t] = 0; }
    for (int j = 0; j < NP; j++) {
        float v = dr[j];
        if (v > vals[KNB - 1]) {
            int p = KNB - 1;
            while (p > 0 && vals[p - 1] < v) {
                vals[p] = vals[p - 1];
                inds[p] = inds[p - 1];
                p--;
            }
            vals[p] = v;
            inds[p] = j;
        }
    }
    for (int t = 0; t < KNB; t++) g_idx[row * KNB + t] = inds[t];
}

__global__ void zero_stats_kernel() {
    int i = threadIdx.x;
    if (i < 682) g_stats[i] = 0.0;
}

// pass1: p = Wa@nbr + (Wb-Wa)@ctr, d likewise; store p,d; accumulate norm stats
__global__ void pass1_kernel(const float* __restrict__ feat, int bstride, int C, int Cout,
                             const float* __restrict__ wf, const float* __restrict__ wd) {
    extern __shared__ float sm[];
    float* sWa   = sm;
    float* sWdel = sWa + Cout * C;
    float* sDa   = sWdel + Cout * C;
    float* sDdel = sDa + Cout * C;
    float* sCtr  = sDdel + Cout * C;
    float* sNbr  = sCtr + C * 3;
    float* sPc   = sNbr + C * 3;
    float* sDc   = sPc + Cout * 3;

    int tid = threadIdx.x;
    int b   = blockIdx.y;
    int n0  = blockIdx.x * NT;

    for (int i = tid; i < Cout * C; i += blockDim.x) {
        int o = i / C, c = i % C;
        float a  = wf[o * 2 * C + c];
        sWa[i]   = a;
        sWdel[i] = wf[o * 2 * C + C + c] - a;
        float da = wd[o * 2 * C + c];
        sDa[i]   = da;
        sDdel[i] = wd[o * 2 * C + C + c] - da;
    }
    __syncthreads();

    const float* F = feat + (size_t)b * bstride;
    double s1 = 0.0, s2 = 0.0;

    for (int nn = 0; nn < NT; nn++) {
        int n = n0 + nn;
        for (int i = tid; i < C * 3; i += blockDim.x) sCtr[i] = F[(size_t)i * NP + n];
        __syncthreads();
        if (tid < Cout) {
            float p0 = 0, p1 = 0, p2 = 0, q0 = 0, q1 = 0, q2 = 0;
            for (int c = 0; c < C; c++) {
                float f0 = sCtr[c * 3], f1 = sCtr[c * 3 + 1], f2 = sCtr[c * 3 + 2];
                float w = sWdel[tid * C + c];
                p0 += w * f0; p1 += w * f1; p2 += w * f2;
                float v = sDdel[tid * C + c];
                q0 += v * f0; q1 += v * f1; q2 += v * f2;
            }
            sPc[tid * 3] = p0; sPc[tid * 3 + 1] = p1; sPc[tid * 3 + 2] = p2;
            sDc[tid * 3] = q0; sDc[tid * 3 + 1] = q1; sDc[tid * 3 + 2] = q2;
        }
        __syncthreads();
        for (int k = 0; k < KNB; k++) {
            int j = g_idx[(b * NP + n) * KNB + k];
            for (int i = tid; i < C * 3; i += blockDim.x) sNbr[i] = F[(size_t)i * NP + j];
            __syncthreads();
            if (tid < Cout) {
                float p0 = sPc[tid * 3], p1 = sPc[tid * 3 + 1], p2 = sPc[tid * 3 + 2];
                float q0 = sDc[tid * 3], q1 = sDc[tid * 3 + 1], q2 = sDc[tid * 3 + 2];
                for (int c = 0; c < C; c++) {
                    float f0 = sNbr[c * 3], f1 = sNbr[c * 3 + 1], f2 = sNbr[c * 3 + 2];
                    float w = sWa[tid * C + c];
                    p0 += w * f0; p1 += w * f1; p2 += w * f2;
                    float v = sDa[tid * C + c];
                    q0 += v * f0; q1 += v * f1; q2 += v * f2;
                }
                size_t base = ((((size_t)(b * NP + n)) * KNB + k) * Cout + tid) * 3;
                g_p[base] = p0; g_p[base + 1] = p1; g_p[base + 2] = p2;
                g_d[base] = q0; g_d[base + 1] = q1; g_d[base + 2] = q2;
                float nor = sqrtf(p0 * p0 + p1 * p1 + p2 * p2) + EPSF;
                s1 += (double)nor;
                s2 += (double)nor * (double)nor;
            }
            __syncthreads();
        }
    }
    if (tid < Cout) {
        atomicAdd(&g_stats[tid], s1);
        atomicAdd(&g_stats[341 + tid], s2);
    }
}

__global__ void bn_finalize_kernel(int Cout, double inv_count) {
    int o = blockIdx.x * blockDim.x + threadIdx.x;
    if (o >= Cout) return;
    double mu  = g_stats[o] * inv_count;
    double var = g_stats[341 + o] * inv_count - mu * mu;
    g_mu[o]   = (float)mu;
    g_rstd[o] = (float)(1.0 / sqrt(var + 1e-5));
}

// pass2: BN + VN-LeakyReLU + mean over k -> write into concat feature buffer
__global__ void pass2_kernel(int cbase_out, int Cout,
                             const float* __restrict__ gamma, const float* __restrict__ beta) {
    int b = blockIdx.y, n = blockIdx.x;
    int o = threadIdx.x;
    if (o >= Cout) return;
    float mu = g_mu[o], rstd = g_rstd[o], gm = gamma[o], bt = beta[o];
    float a0 = 0, a1 = 0, a2 = 0;
    for (int k = 0; k < KNB; k++) {
        size_t base = ((((size_t)(b * NP + n)) * KNB + k) * Cout + o) * 3;
        float p0 = g_p[base], p1 = g_p[base + 1], p2 = g_p[base + 2];
        float d0 = g_d[base], d1 = g_d[base + 1], d2 = g_d[base + 2];
        float nor = sqrtf(p0 * p0 + p1 * p1 + p2 * p2) + EPSF;
        float s = ((nor - mu) * rstd * gm + bt) / nor;
        p0 *= s; p1 *= s; p2 *= s;
        float dot = p0 * d0 + p1 * d1 + p2 * d2;
        if (dot >= 0.f) {
            a0 += p0; a1 += p1; a2 += p2;
        } else {
            float dsq = d0 * d0 + d1 * d1 + d2 * d2;
            float f = 0.8f * dot / (dsq + EPSF);
            a0 += p0 - f * d0; a1 += p1 - f * d1; a2 += p2 - f * d2;
        }
    }
    const float inv = 1.f / (float)KNB;
    float* FO = g_feat + ((size_t)b * CT + cbase_out + o) * 3 * NP;
    FO[0 * NP + n] = a0 * inv;
    FO[1 * NP + n] = a1 * inv;
    FO[2 * NP + n] = a2 * inv;
}

// layer 5: p5[b] (341x3072) = w5 (341x169) @ feat[b] (169x3072), into g_p
__global__ void gemm_l5_kernel(const float* __restrict__ w5) {
    __shared__ float As[32][33];
    __shared__ float Bs[32][33];
    int b = blockIdx.z;
    const float* Bm = g_feat + (size_t)b * CT * 3 * NP;
    float* Cm = g_p + (size_t)b * 341 * 3072;
    int tx = threadIdx.x, ty = threadIdx.y;
    int row = blockIdx.y * 32 + ty;
    int col = blockIdx.x * 32 + tx;
    float acc = 0.f;
    for (int k0 = 0; k0 < CT; k0 += 32) {
        int ac = k0 + tx;
        As[ty][tx] = (row < 341 && ac < CT) ? w5[row * CT + ac] : 0.f;
        int br = k0 + ty;
        Bs[ty][tx] = (br < CT) ? Bm[(size_t)br * 3072 + col] : 0.f;
        __syncthreads();
#pragma unroll
        for (int q = 0; q < 32; q++) acc += As[ty][q] * Bs[q][tx];
        __syncthreads();
    }
    if (row < 341) Cm[(size_t)row * 3072 + col] = acc;
}

__global__ void d5_kernel(const float* __restrict__ wd5) {
    int i = blockIdx.x * blockDim.x + threadIdx.x;   // B*3*N
    if (i >= BSZ * 3 * NP) return;
    int n = i % NP;
    int e = (i / NP) % 3;
    int b = i / (3 * NP);
    const float* F = g_feat + (size_t)b * CT * 3 * NP;
    float a = 0.f;
    for (int c = 0; c < CT; c++) a += wd5[c] * F[(size_t)(c * 3 + e) * NP + n];
    g_d[(size_t)b * 3072 + e * NP + n] = a;
}

__global__ void stats5_kernel() {
    int o = blockIdx.x, b = blockIdx.y;
    const float* P = g_p + ((size_t)b * 341 + o) * 3072;
    double s1 = 0.0, s2 = 0.0;
    for (int n = threadIdx.x; n < NP; n += blockDim.x) {
        float p0 = P[n], p1 = P[NP + n], p2 = P[2 * NP + n];
        float nor = sqrtf(p0 * p0 + p1 * p1 + p2 * p2) + EPSF;
        s1 += (double)nor;
        s2 += (double)nor * (double)nor;
    }
#pragma unroll
    for (int off = 16; off > 0; off >>= 1) {
        s1 += __shfl_down_sync(0xffffffff, s1, off);
        s2 += __shfl_down_sync(0xffffffff, s2, off);
    }
    if ((threadIdx.x & 31) == 0) {
        atomicAdd(&g_stats[o], s1);
        atomicAdd(&g_stats[341 + o], s2);
    }
}

__global__ void pass2_l5_kernel(float* __restrict__ out,
                                const float* __restrict__ gamma, const float* __restrict__ beta) {
    int i = blockIdx.x * blockDim.x + threadIdx.x;  // over B*341*N
    if (i >= BSZ * 341 * NP) return;
    int n = i % NP;
    int o = (i / NP) % 341;
    int b = i / (341 * NP);
    const float* P = g_p + ((size_t)b * 341 + o) * 3072;
    const float* D = g_d + (size_t)b * 3072;
    float p0 = P[n], p1 = P[NP + n], p2 = P[2 * NP + n];
    float d0 = D[n], d1 = D[NP + n], d2 = D[2 * NP + n];
    float nor = sqrtf(p0 * p0 + p1 * p1 + p2 * p2) + EPSF;
    float s = ((nor - g_mu[o]) * g_rstd[o] * gamma[o] + beta[o]) / nor;
    p0 *= s; p1 *= s; p2 *= s;
    float dot = p0 * d0 + p1 * d1 + p2 * d2;
    float v0, v1, v2;
    if (dot >= 0.f) {
        v0 = p0; v1 = p1; v2 = p2;
    } else {
        float dsq = d0 * d0 + d1 * d1 + d2 * d2;
        float f = 0.8f * dot / (dsq + EPSF);
        v0 = p0 - f * d0; v1 = p1 - f * d1; v2 = p2 - f * d2;
    }
    size_t ob = ((size_t)b * 341 + o) * 3072;
    out[ob + 0 * NP + n] = v0;
    out[ob + 1 * NP + n] = v1;
    out[ob + 2 * NP + n] = v2;
}

// ---------------- launch ----------------
extern "C" void kernel_launch(void* const* d_in, const int* in_sizes, int n_in,
                              void* d_out, int out_size) {
    const float* x = (const float*)d_in[0];
    const float *W[5], *Dw[5], *G[5], *Bt[5];
    for (int l = 0; l < 5; l++) {
        W[l]  = (const float*)d_in[1 + 4 * l];
        Dw[l] = (const float*)d_in[2 + 4 * l];
        G[l]  = (const float*)d_in[3 + 4 * l];
        Bt[l] = (const float*)d_in[4 + 4 * l];
    }
    float* out = (float*)d_out;

    void* pv;
    cudaGetSymbolAddress(&pv, g_h);
    float* hptr = (float*)pv;
    cudaGetSymbolAddress(&pv, g_feat);
    float* fptr = (float*)pv;

    cudaFuncSetAttribute(pass1_kernel, cudaFuncAttributeMaxDynamicSharedMemorySize, 64 * 1024);

    transpose_x_kernel<<<96, 256>>>(x);

    struct LayerCfg { const float* feat; int D; int C; int Cout; int cbo; };
    LayerCfg L[4] = {
        { hptr,                 3,   1,  21, 0  },
        { fptr,                 63,  21, 21, 21 },
        { fptr + 21 * 3 * NP,   63,  21, 42, 42 },
        { fptr + 42 * 3 * NP,   126, 42, 85, 84 },
    };

    for (int l = 0; l < 4; l++) {
        int bstride = (l == 0) ? 3 * NP : CT * 3 * NP;
        xx_kernel<<<dim3(NP / 256, BSZ), 256>>>(L[l].feat, bstride, L[l].D);
        knn_dist_kernel<<<dim3(NP / 32, NP / 32, BSZ), dim3(32, 8)>>>(L[l].feat, bstride, L[l].D);
        knn_topk_kernel<<<BSZ * NP / 128, 128>>>();
        zero_stats_kernel<<<1, 682>>>();
        int C = L[l].C, Co = L[l].Cout;
        size_t smem = (size_t)(4 * Co * C + 2 * C * 3 + 2 * Co * 3) * sizeof(float);
        pass1_kernel<<<dim3(NP / NT, BSZ), 128, smem>>>(L[l].feat, bstride, C, Co, W[l], Dw[l]);
        bn_finalize_kernel<<<3, 128>>>(Co, 1.0 / ((double)BSZ * NP * KNB));
        pass2_kernel<<<dim3(NP, BSZ), 128>>>(L[l].cbo, Co, G[l], Bt[l]);
    }

    // layer 5
    zero_stats_kernel<<<1, 682>>>();
    gemm_l5_kernel<<<dim3(3072 / 32, (341 + 31) / 32, BSZ), dim3(32, 32)>>>(W[4]);
    d5_kernel<<<96, 256>>>(Dw[4]);
    stats5_kernel<<<dim3(341, BSZ), 256>>>();
    bn_finalize_kernel<<<3, 128>>>(341, 1.0 / ((double)BSZ * NP));
    pass2_l5_kernel<<<(BSZ * 341 * NP + 255) / 256, 256>>>(out, G[4], Bt[4]);
}

// round 4
// speedup vs baseline: 1.0929x; 1.0929x over previous
#include <cuda_runtime.h>
#include <math.h>
#include <float.h>

#define BSZ 8
#define NP  1024
#define KNB 20
#define CT  169
#define EPSF 1e-6f
#define NT  8

// ---------------- scratch (device globals; no runtime allocation) ----------------
__device__ float  g_h[BSZ * 3 * NP];
__device__ float  g_xx[BSZ * NP];
__device__ float  g_dist[(size_t)BSZ * NP * NP];           // 32 MB distance matrix (L2-resident)
__device__ int    g_idx[BSZ * NP * KNB];
__device__ float  g_feat[BSZ * CT * 3 * NP];               // x1|x2|x3|x4 concat channels
__device__ float  g_p[(size_t)BSZ * NP * KNB * 85 * 3];    // 167 MB  (reused as p5)
__device__ float  g_d[(size_t)BSZ * NP * KNB * 85 * 3];    // 167 MB  (reused as d5)
__device__ double g_stats[682];
__device__ float  g_mu[341];
__device__ float  g_rstd[341];

// ---------------- kernels ----------------

__global__ void transpose_x_kernel(const float* __restrict__ x) {
    int i = blockIdx.x * blockDim.x + threadIdx.x;   // over B*N*3
    if (i >= BSZ * NP * 3) return;
    int e = i % 3;
    int n = (i / 3) % NP;
    int b = i / (3 * NP);
    g_h[(b * 3 + e) * NP + n] = x[i];
}

__global__ void xx_kernel(const float* __restrict__ f, int bstride, int D) {
    int b = blockIdx.y;
    int n = blockIdx.x * blockDim.x + threadIdx.x;
    const float* fb = f + (size_t)b * bstride;
    float s = 0.f;
    for (int d = 0; d < D; d++) {
        float v = fb[d * NP + n];
        s += v * v;
    }
    g_xx[b * NP + n] = s;
}

// pd[b][i][j] = 2*dot(f_i,f_j) - xx_i - xx_j   (== reference formula)
__global__ void knn_dist_kernel(const float* __restrict__ f, int bstride, int D) {
    __shared__ float sI[8][32];
    __shared__ float sJ[8][32];
    int b  = blockIdx.z;
    int j0 = blockIdx.x * 32;
    int i0 = blockIdx.y * 32;
    int tx = threadIdx.x, ty = threadIdx.y;
    const float* fb = f + (size_t)b * bstride;
    float acc[4] = {0.f, 0.f, 0.f, 0.f};
    for (int d0 = 0; d0 < D; d0 += 8) {
        int d = d0 + ty;
        sI[ty][tx] = (d < D) ? fb[d * NP + i0 + tx] : 0.f;
        sJ[ty][tx] = (d < D) ? fb[d * NP + j0 + tx] : 0.f;
        __syncthreads();
#pragma unroll
        for (int dd = 0; dd < 8; dd++) {
            float vj = sJ[dd][tx];
#pragma unroll
            for (int r = 0; r < 4; r++) acc[r] += sI[dd][ty + 8 * r] * vj;
        }
        __syncthreads();
    }
    float xj = g_xx[b * NP + j0 + tx];
#pragma unroll
    for (int r = 0; r < 4; r++) {
        int i = i0 + ty + 8 * r;
        g_dist[((size_t)b * NP + i) * NP + j0 + tx] = 2.f * acc[r] - g_xx[b * NP + i] - xj;
    }
}

// warp-per-row stable top-K (ties -> lower index, matching jax.lax.top_k)
__global__ void knn_topk_kernel() {
    int gw   = (blockIdx.x * blockDim.x + threadIdx.x) >> 5;   // warp id == row
    int lane = threadIdx.x & 31;
    if (gw >= BSZ * NP) return;
    const float* dr = &g_dist[(size_t)gw * NP];

    // phase 1: per-lane stable top-K over its stride-32 partition (indices ascending)
    float vals[KNB];
    int   inds[KNB];
#pragma unroll
    for (int t = 0; t < KNB; t++) { vals[t] = -FLT_MAX; inds[t] = 0x7fffffff; }
#pragma unroll 4
    for (int t = 0; t < NP / 32; t++) {
        int j = lane + 32 * t;
        float v = dr[j];
        if (v > vals[KNB - 1]) {
            int p = KNB - 1;
            while (p > 0 && vals[p - 1] < v) {
                vals[p] = vals[p - 1];
                inds[p] = inds[p - 1];
                p--;
            }
            vals[p] = v;
            inds[p] = j;
        }
    }

    // phase 2: 20-round warp merge (argmax with lower-index tiebreak)
    int ptr = 0;
    for (int t = 0; t < KNB; t++) {
        float v = (ptr < KNB) ? vals[ptr] : -FLT_MAX;
        int   j = (ptr < KNB) ? inds[ptr] : 0x7fffffff;
#pragma unroll
        for (int off = 16; off > 0; off >>= 1) {
            float v2 = __shfl_down_sync(0xffffffffu, v, off);
            int   j2 = __shfl_down_sync(0xffffffffu, j, off);
            if (v2 > v || (v2 == v && j2 < j)) { v = v2; j = j2; }
        }
        j = __shfl_sync(0xffffffffu, j, 0);
        if (lane == 0) g_idx[gw * KNB + t] = j;
        if ((j & 31) == lane) ptr++;   // winner lane advances its head
    }
}

__global__ void zero_stats_kernel() {
    int i = threadIdx.x;
    if (i < 682) g_stats[i] = 0.0;
}

// pass1: thread = (o, e).  p = Wa@nbr + (Wb-Wa)@ctr, d likewise; store p,d; norm stats
__global__ void pass1_kernel(const float* __restrict__ feat, int bstride, int C, int Cout,
                             const float* __restrict__ wf, const float* __restrict__ wd) {
    extern __shared__ float sm[];
    float* sWa   = sm;                    // Cout*C
    float* sWdel = sWa + Cout * C;
    float* sDa   = sWdel + Cout * C;
    float* sDdel = sDa + Cout * C;
    float* sCtr  = sDdel + Cout * C;      // C*3
    float* sNbr  = sCtr + C * 3;          // C*3
    float* sP    = sNbr + C * 3;          // Cout*3

    int tid = threadIdx.x;
    int b   = blockIdx.y;
    int n0  = blockIdx.x * NT;
    int o = tid / 3, e = tid % 3;
    bool act = (tid < Cout * 3);

    for (int i = tid; i < Cout * C; i += blockDim.x) {
        int oo = i / C, c = i % C;
        float a  = wf[oo * 2 * C + c];
        sWa[i]   = a;
        sWdel[i] = wf[oo * 2 * C + C + c] - a;
        float da = wd[oo * 2 * C + c];
        sDa[i]   = da;
        sDdel[i] = wd[oo * 2 * C + C + c] - da;
    }
    __syncthreads();

    const float* F = feat + (size_t)b * bstride;
    double s1 = 0.0, s2 = 0.0;

    for (int nn = 0; nn < NT; nn++) {
        int n = n0 + nn;
        __syncthreads();
        for (int i = tid; i < C * 3; i += blockDim.x) sCtr[i] = F[(size_t)i * NP + n];
        __syncthreads();
        float pc = 0.f, qc = 0.f;
        if (act) {
            const float* wr = &sWdel[o * C];
            const float* vr = &sDdel[o * C];
            for (int c = 0; c < C; c++) {
                float fv = sCtr[c * 3 + e];
                pc += wr[c] * fv;
                qc += vr[c] * fv;
            }
        }
        for (int k = 0; k < KNB; k++) {
            int j = g_idx[(b * NP + n) * KNB + k];
            __syncthreads();   // prev stats read of sP / prev compute read of sNbr done
            for (int i = tid; i < C * 3; i += blockDim.x) sNbr[i] = F[(size_t)i * NP + j];
            __syncthreads();
            if (act) {
                float p = pc, q = qc;
                const float* wr = &sWa[o * C];
                const float* vr = &sDa[o * C];
                for (int c = 0; c < C; c++) {
                    float fv = sNbr[c * 3 + e];
                    p += wr[c] * fv;
                    q += vr[c] * fv;
                }
                size_t base = ((((size_t)(b * NP + n)) * KNB + k) * Cout) * 3 + tid;
                g_p[base] = p;
                g_d[base] = q;
                sP[tid] = p;
            }
            __syncthreads();
            if (tid < Cout) {
                float p0 = sP[tid * 3], p1 = sP[tid * 3 + 1], p2 = sP[tid * 3 + 2];
                float nor = sqrtf(p0 * p0 + p1 * p1 + p2 * p2) + EPSF;
                s1 += (double)nor;
                s2 += (double)nor * (double)nor;
            }
        }
    }
    if (tid < Cout) {
        atomicAdd(&g_stats[tid], s1);
        atomicAdd(&g_stats[341 + tid], s2);
    }
}

__global__ void bn_finalize_kernel(int Cout, double inv_count) {
    int o = blockIdx.x * blockDim.x + threadIdx.x;
    if (o >= Cout) return;
    double mu  = g_stats[o] * inv_count;
    double var = g_stats[341 + o] * inv_count - mu * mu;
    g_mu[o]   = (float)mu;
    g_rstd[o] = (float)(1.0 / sqrt(var + 1e-5));
}

// pass2: BN + VN-LeakyReLU + mean over k -> write into concat feature buffer
__global__ void pass2_kernel(int cbase_out, int Cout,
                             const float* __restrict__ gamma, const float* __restrict__ beta) {
    int b = blockIdx.y, n = blockIdx.x;
    int o = threadIdx.x;
    if (o >= Cout) return;
    float mu = g_mu[o], rstd = g_rstd[o], gm = gamma[o], bt = beta[o];
    float a0 = 0, a1 = 0, a2 = 0;
    for (int k = 0; k < KNB; k++) {
        size_t base = ((((size_t)(b * NP + n)) * KNB + k) * Cout + o) * 3;
        float p0 = g_p[base], p1 = g_p[base + 1], p2 = g_p[base + 2];
        float d0 = g_d[base], d1 = g_d[base + 1], d2 = g_d[base + 2];
        float nor = sqrtf(p0 * p0 + p1 * p1 + p2 * p2) + EPSF;
        float s = ((nor - mu) * rstd * gm + bt) / nor;
        p0 *= s; p1 *= s; p2 *= s;
        float dot = p0 * d0 + p1 * d1 + p2 * d2;
        if (dot >= 0.f) {
            a0 += p0; a1 += p1; a2 += p2;
        } else {
            float dsq = d0 * d0 + d1 * d1 + d2 * d2;
            float f = 0.8f * dot / (dsq + EPSF);
            a0 += p0 - f * d0; a1 += p1 - f * d1; a2 += p2 - f * d2;
        }
    }
    const float inv = 1.f / (float)KNB;
    float* FO = g_feat + ((size_t)b * CT + cbase_out + o) * 3 * NP;
    FO[0 * NP + n] = a0 * inv;
    FO[1 * NP + n] = a1 * inv;
    FO[2 * NP + n] = a2 * inv;
}

// layer 5: p5[b] (341x3072) = w5 (341x169) @ feat[b] (169x3072), into g_p
__global__ void gemm_l5_kernel(const float* __restrict__ w5) {
    __shared__ float As[32][33];
    __shared__ float Bs[32][33];
    int b = blockIdx.z;
    const float* Bm = g_feat + (size_t)b * CT * 3 * NP;
    float* Cm = g_p + (size_t)b * 341 * 3072;
    int tx = threadIdx.x, ty = threadIdx.y;
    int row = blockIdx.y * 32 + ty;
    int col = blockIdx.x * 32 + tx;
    float acc = 0.f;
    for (int k0 = 0; k0 < CT; k0 += 32) {
        int ac = k0 + tx;
        As[ty][tx] = (row < 341 && ac < CT) ? w5[row * CT + ac] : 0.f;
        int br = k0 + ty;
        Bs[ty][tx] = (br < CT) ? Bm[(size_t)br * 3072 + col] : 0.f;
        __syncthreads();
#pragma unroll
        for (int q = 0; q < 32; q++) acc += As[ty][q] * Bs[q][tx];
        __syncthreads();
    }
    if (row < 341) Cm[(size_t)row * 3072 + col] = acc;
}

__global__ void d5_kernel(const float* __restrict__ wd5) {
    int i = blockIdx.x * blockDim.x + threadIdx.x;   // B*3*N
    if (i >= BSZ * 3 * NP) return;
    int n = i % NP;
    int e = (i / NP) % 3;
    int b = i / (3 * NP);
    const float* F = g_feat + (size_t)b * CT * 3 * NP;
    float a = 0.f;
    for (int c = 0; c < CT; c++) a += wd5[c] * F[(size_t)(c * 3 + e) * NP + n];
    g_d[(size_t)b * 3072 + e * NP + n] = a;
}

__global__ void stats5_kernel() {
    int o = blockIdx.x, b = blockIdx.y;
    const float* P = g_p + ((size_t)b * 341 + o) * 3072;
    double s1 = 0.0, s2 = 0.0;
    for (int n = threadIdx.x; n < NP; n += blockDim.x) {
        float p0 = P[n], p1 = P[NP + n], p2 = P[2 * NP + n];
        float nor = sqrtf(p0 * p0 + p1 * p1 + p2 * p2) + EPSF;
        s1 += (double)nor;
        s2 += (double)nor * (double)nor;
    }
#pragma unroll
    for (int off = 16; off > 0; off >>= 1) {
        s1 += __shfl_down_sync(0xffffffff, s1, off);
        s2 += __shfl_down_sync(0xffffffff, s2, off);
    }
    if ((threadIdx.x & 31) == 0) {
        atomicAdd(&g_stats[o], s1);
        atomicAdd(&g_stats[341 + o], s2);
    }
}

__global__ void pass2_l5_kernel(float* __restrict__ out,
                                const float* __restrict__ gamma, const float* __restrict__ beta) {
    int i = blockIdx.x * blockDim.x + threadIdx.x;  // over B*341*N
    if (i >= BSZ * 341 * NP) return;
    int n = i % NP;
    int o = (i / NP) % 341;
    int b = i / (341 * NP);
    const float* P = g_p + ((size_t)b * 341 + o) * 3072;
    const float* D = g_d + (size_t)b * 3072;
    float p0 = P[n], p1 = P[NP + n], p2 = P[2 * NP + n];
    float d0 = D[n], d1 = D[NP + n], d2 = D[2 * NP + n];
    float nor = sqrtf(p0 * p0 + p1 * p1 + p2 * p2) + EPSF;
    float s = ((nor - g_mu[o]) * g_rstd[o] * gamma[o] + beta[o]) / nor;
    p0 *= s; p1 *= s; p2 *= s;
    float dot = p0 * d0 + p1 * d1 + p2 * d2;
    float v0, v1, v2;
    if (dot >= 0.f) {
        v0 = p0; v1 = p1; v2 = p2;
    } else {
        float dsq = d0 * d0 + d1 * d1 + d2 * d2;
        float f = 0.8f * dot / (dsq + EPSF);
        v0 = p0 - f * d0; v1 = p1 - f * d1; v2 = p2 - f * d2;
    }
    size_t ob = ((size_t)b * 341 + o) * 3072;
    out[ob + 0 * NP + n] = v0;
    out[ob + 1 * NP + n] = v1;
    out[ob + 2 * NP + n] = v2;
}

// ---------------- launch ----------------
extern "C" void kernel_launch(void* const* d_in, const int* in_sizes, int n_in,
                              void* d_out, int out_size) {
    const float* x = (const float*)d_in[0];
    const float *W[5], *Dw[5], *G[5], *Bt[5];
    for (int l = 0; l < 5; l++) {
        W[l]  = (const float*)d_in[1 + 4 * l];
        Dw[l] = (const float*)d_in[2 + 4 * l];
        G[l]  = (const float*)d_in[3 + 4 * l];
        Bt[l] = (const float*)d_in[4 + 4 * l];
    }
    float* out = (float*)d_out;

    void* pv;
    cudaGetSymbolAddress(&pv, g_h);
    float* hptr = (float*)pv;
    cudaGetSymbolAddress(&pv, g_feat);
    float* fptr = (float*)pv;

    cudaFuncSetAttribute(pass1_kernel, cudaFuncAttributeMaxDynamicSharedMemorySize, 64 * 1024);

    transpose_x_kernel<<<96, 256>>>(x);

    struct LayerCfg { const float* feat; int D; int C; int Cout; int cbo; };
    LayerCfg L[4] = {
        { hptr,                 3,   1,  21, 0  },
        { fptr,                 63,  21, 21, 21 },
        { fptr + 21 * 3 * NP,   63,  21, 42, 42 },
        { fptr + 42 * 3 * NP,   126, 42, 85, 84 },
    };

    for (int l = 0; l < 4; l++) {
        int bstride = (l == 0) ? 3 * NP : CT * 3 * NP;
        xx_kernel<<<dim3(NP / 256, BSZ), 256>>>(L[l].feat, bstride, L[l].D);
        knn_dist_kernel<<<dim3(NP / 32, NP / 32, BSZ), dim3(32, 8)>>>(L[l].feat, bstride, L[l].D);
        knn_topk_kernel<<<BSZ * NP * 32 / 256, 256>>>();
        zero_stats_kernel<<<1, 682>>>();
        int C = L[l].C, Co = L[l].Cout;
        size_t smem = (size_t)(4 * Co * C + 2 * C * 3 + Co * 3) * sizeof(float);
        pass1_kernel<<<dim3(NP / NT, BSZ), 256, smem>>>(L[l].feat, bstride, C, Co, W[l], Dw[l]);
        bn_finalize_kernel<<<3, 128>>>(Co, 1.0 / ((double)BSZ * NP * KNB));
        pass2_kernel<<<dim3(NP, BSZ), 128>>>(L[l].cbo, Co, G[l], Bt[l]);
    }

    // layer 5
    zero_stats_kernel<<<1, 682>>>();
    gemm_l5_kernel<<<dim3(3072 / 32, (341 + 31) / 32, BSZ), dim3(32, 32)>>>(W[4]);
    d5_kernel<<<96, 256>>>(Dw[4]);
    stats5_kernel<<<dim3(341, BSZ), 256>>>();
    bn_finalize_kernel<<<3, 128>>>(341, 1.0 / ((double)BSZ * NP));
    pass2_l5_kernel<<<(BSZ * 341 * NP + 255) / 256, 256>>>(out, G[4], Bt[4]);
}